// round 2
// baseline (speedup 1.0000x reference)
#include <cuda_runtime.h>
#include <math.h>

// Problem constants
#define D_MODEL 1024
#define VOCAB   32000
#define BB      2
#define TT      2048
#define M_TOT   (BB * TT)      // 4096
#define D_FF    (4 * D_MODEL)  // 4096

// ---------------------------------------------------------------------------
// Scratch (static __device__ arrays; no allocation allowed)
// ---------------------------------------------------------------------------
__device__ float g_x[M_TOT * D_MODEL];     // 16 MB  residual stream
__device__ float g_q[M_TOT * D_MODEL];     // 16 MB
__device__ float g_k[M_TOT * D_MODEL];     // 16 MB
__device__ float g_v[M_TOT * D_MODEL];     // 16 MB
__device__ float g_s[BB * TT * TT];        // 32 MB  scores / attn (in-place)
__device__ float g_h[M_TOT * D_FF];        // 64 MB  MLP hidden

// ---------------------------------------------------------------------------
// Embedding: x[b,t,:] = tok_emb[idx[b,t],:] + pos_emb[t,:]
// ---------------------------------------------------------------------------
__global__ void embed_kernel(const int* __restrict__ idx,
                             const float* __restrict__ tok,
                             const float* __restrict__ pos) {
    int i = blockIdx.x * blockDim.x + threadIdx.x;   // over M_TOT*D_MODEL/4
    int n4 = (M_TOT * D_MODEL) / 4;
    if (i >= n4) return;
    int e   = i * 4;
    int row = e / D_MODEL;
    int d   = e % D_MODEL;
    int t   = row % TT;
    int tk  = idx[row];
    const float4 a = *reinterpret_cast<const float4*>(tok + (long)tk * D_MODEL + d);
    const float4 b = *reinterpret_cast<const float4*>(pos + (long)t  * D_MODEL + d);
    float4 o;
    o.x = a.x + b.x; o.y = a.y + b.y; o.z = a.z + b.z; o.w = a.w + b.w;
    *reinterpret_cast<float4*>(g_x + e) = o;
}

// ---------------------------------------------------------------------------
// Tiled SGEMM: C = epi(alpha * A @ B(^T) [+ bias]) [res + res_scale * (...)]
//   A: [M,K] row-major.  B: [K,N] row-major, or [N,K] row-major if TRANSB.
//   BM=BN=128, BK=8, 8x8 per thread, 256 threads.
//   All M,N multiples of 128; K multiple of 8 (true for every call site).
//   blockIdx.z batches with the given strides.
// ---------------------------------------------------------------------------
template<bool TRANSB, bool HAS_BIAS, bool GELU, bool HAS_RES>
__global__ __launch_bounds__(256)
void sgemm(const float* __restrict__ A, const float* __restrict__ Bm,
           const float* __restrict__ bias, const float* __restrict__ Res,
           float* __restrict__ C, int M, int N, int K,
           float alpha, float res_scale,
           long sA, long sB, long sC, long sR)
{
    constexpr int BM = 128, BN = 128, BK = 8, TM = 8, TN = 8;

    A  += (long)blockIdx.z * sA;
    Bm += (long)blockIdx.z * sB;
    C  += (long)blockIdx.z * sC;
    if (HAS_RES) Res += (long)blockIdx.z * sR;

    __shared__ float As[BK][BM];
    __shared__ float Bs[BK][BN];

    const int tid  = threadIdx.x;
    const int cRow = blockIdx.y * BM;
    const int cCol = blockIdx.x * BN;

    const int tr = (tid / 16) * TM;   // 0..120
    const int tc = (tid % 16) * TN;   // 0..120

    float acc[TM][TN];
#pragma unroll
    for (int i = 0; i < TM; i++)
#pragma unroll
        for (int j = 0; j < TN; j++) acc[i][j] = 0.f;

    const int aRow0 = tid / BK;   // 0..31 (stride 32, 4 iters)
    const int aCol  = tid % BK;   // 0..7
    const int bRow0 = tid / BN;   // 0..1  (stride 2, 4 iters)
    const int bCol  = tid % BN;   // 0..127

    for (int kt = 0; kt < K; kt += BK) {
#pragma unroll
        for (int i = 0; i < 4; i++) {
            int m = aRow0 + i * 32;
            As[aCol][m] = A[(long)(cRow + m) * K + kt + aCol];
        }
        if (!TRANSB) {
#pragma unroll
            for (int i = 0; i < 4; i++) {
                int kk = bRow0 + i * 2;
                Bs[kk][bCol] = Bm[(long)(kt + kk) * N + cCol + bCol];
            }
        } else {
#pragma unroll
            for (int i = 0; i < 4; i++) {
                int n = aRow0 + i * 32;
                Bs[aCol][n] = Bm[(long)(cCol + n) * K + kt + aCol];
            }
        }
        __syncthreads();

#pragma unroll
        for (int kk = 0; kk < BK; kk++) {
            float ra[TM], rb[TN];
#pragma unroll
            for (int i = 0; i < TM; i++) ra[i] = As[kk][tr + i];
#pragma unroll
            for (int j = 0; j < TN; j++) rb[j] = Bs[kk][tc + j];
#pragma unroll
            for (int i = 0; i < TM; i++)
#pragma unroll
                for (int j = 0; j < TN; j++)
                    acc[i][j] += ra[i] * rb[j];
        }
        __syncthreads();
    }

#pragma unroll
    for (int i = 0; i < TM; i++) {
        long row = cRow + tr + i;
#pragma unroll
        for (int j = 0; j < TN; j++) {
            long col = cCol + tc + j;
            float v = alpha * acc[i][j];
            if (HAS_BIAS) v += bias[col];
            if (GELU)     v = 0.5f * v * (1.0f + erff(v * 0.70710678118f));
            if (HAS_RES)  v = Res[row * N + col] + res_scale * v;
            C[row * N + col] = v;
        }
    }
}

// ---------------------------------------------------------------------------
// Causal row softmax, in place on g_s. One block per (b,q) row.
// Positions j > q get attn = 0.
// ---------------------------------------------------------------------------
__global__ void softmax_causal(float* __restrict__ s) {
    const int row = blockIdx.x;           // b*TT + q
    const int q   = row % TT;
    float* p = s + (long)row * TT;
    const int n = q + 1;
    const int tid = threadIdx.x;
    __shared__ float red[256];

    float m = -INFINITY;
    for (int j = tid; j < n; j += 256) m = fmaxf(m, p[j]);
    red[tid] = m; __syncthreads();
    for (int st = 128; st > 0; st >>= 1) {
        if (tid < st) red[tid] = fmaxf(red[tid], red[tid + st]);
        __syncthreads();
    }
    m = red[0]; __syncthreads();

    float sum = 0.f;
    for (int j = tid; j < n; j += 256) {
        float e = __expf(p[j] - m);
        p[j] = e;
        sum += e;
    }
    red[tid] = sum; __syncthreads();
    for (int st = 128; st > 0; st >>= 1) {
        if (tid < st) red[tid] += red[tid + st];
        __syncthreads();
    }
    const float inv = 1.0f / red[0];
    __syncthreads();

    for (int j = tid; j < n; j += 256) p[j] *= inv;
    for (int j = n + tid; j < TT; j += 256) p[j] = 0.f;
}

// ---------------------------------------------------------------------------
// Launch
// ---------------------------------------------------------------------------
extern "C" void kernel_launch(void* const* d_in, const int* in_sizes, int n_in,
                              void* d_out, int out_size) {
    const int*   idx  = (const int*)d_in[0];
    const float* tok  = (const float*)d_in[1];
    const float* pos  = (const float*)d_in[2];
    const float* Wq   = (const float*)d_in[3];
    const float* Wk   = (const float*)d_in[4];
    const float* Wv   = (const float*)d_in[5];
    const float* W1   = (const float*)d_in[6];
    const float* b1   = (const float*)d_in[7];
    const float* W2   = (const float*)d_in[8];
    const float* b2   = (const float*)d_in[9];
    const float* Wout = (const float*)d_in[10];
    const float* bout = (const float*)d_in[11];
    float* out = (float*)d_out;

    float *x, *q, *k, *v, *s, *h;
    cudaGetSymbolAddress((void**)&x, g_x);
    cudaGetSymbolAddress((void**)&q, g_q);
    cudaGetSymbolAddress((void**)&k, g_k);
    cudaGetSymbolAddress((void**)&v, g_v);
    cudaGetSymbolAddress((void**)&s, g_s);
    cudaGetSymbolAddress((void**)&h, g_h);

    // 1. embeddings -> g_x
    {
        int n4 = (M_TOT * D_MODEL) / 4;
        embed_kernel<<<(n4 + 255) / 256, 256>>>(idx, tok, pos);
    }

    // 2. q,k,v = x @ W{q,k,v}   [4096,1024]x[1024,1024]
    {
        dim3 grid(D_MODEL / 128, M_TOT / 128, 1);
        sgemm<false,false,false,false><<<grid, 256>>>(x, Wq, nullptr, nullptr, q,
            M_TOT, D_MODEL, D_MODEL, 1.0f, 0.f, 0, 0, 0, 0);
        sgemm<false,false,false,false><<<grid, 256>>>(x, Wk, nullptr, nullptr, k,
            M_TOT, D_MODEL, D_MODEL, 1.0f, 0.f, 0, 0, 0, 0);
        sgemm<false,false,false,false><<<grid, 256>>>(x, Wv, nullptr, nullptr, v,
            M_TOT, D_MODEL, D_MODEL, 1.0f, 0.f, 0, 0, 0, 0);
    }

    // 3. scores = (q @ k^T) * (1/sqrt(D))  per batch  [2048,1024]x[2048,1024]^T
    {
        dim3 grid(TT / 128, TT / 128, BB);
        sgemm<true,false,false,false><<<grid, 256>>>(q, k, nullptr, nullptr, s,
            TT, TT, D_MODEL, 1.0f / 32.0f, 0.f,
            (long)TT * D_MODEL, (long)TT * D_MODEL, (long)TT * TT, 0);
    }

    // 4. causal softmax (in place)
    softmax_causal<<<BB * TT, 256>>>(s);

    // 5. x = x + 0.125 * (attn @ v)  per batch  [2048,2048]x[2048,1024]
    {
        dim3 grid(D_MODEL / 128, TT / 128, BB);
        sgemm<false,false,false,true><<<grid, 256>>>(s, v, nullptr, x, x,
            TT, D_MODEL, TT, 1.0f, 0.125f,
            (long)TT * TT, (long)TT * D_MODEL, (long)TT * D_MODEL, (long)TT * D_MODEL);
    }

    // 6. h = gelu(x @ W1 + b1)   [4096,1024]x[1024,4096]
    {
        dim3 grid(D_FF / 128, M_TOT / 128, 1);
        sgemm<false,true,true,false><<<grid, 256>>>(x, W1, b1, nullptr, h,
            M_TOT, D_FF, D_MODEL, 1.0f, 0.f, 0, 0, 0, 0);
    }

    // 7. x = x + (h @ W2 + b2)   [4096,4096]x[4096,1024]
    {
        dim3 grid(D_MODEL / 128, M_TOT / 128, 1);
        sgemm<false,true,false,true><<<grid, 256>>>(h, W2, b2, x, x,
            M_TOT, D_MODEL, D_FF, 1.0f, 1.0f, 0, 0, 0, 0);
    }

    // 8. out = x @ Wout + bout   [4096,1024]x[1024,32000]
    {
        dim3 grid(VOCAB / 128, M_TOT / 128, 1);
        sgemm<false,true,false,false><<<grid, 256>>>(x, Wout, bout, nullptr, out,
            M_TOT, VOCAB, D_MODEL, 1.0f, 0.f, 0, 0, 0, 0);
    }
}

// round 3
// speedup vs baseline: 1.4593x; 1.4593x over previous
#include <cuda_runtime.h>
#include <mma.h>
#include <math.h>

using namespace nvcuda;

// Problem constants
#define D_MODEL 1024
#define VOCAB   32000
#define BB      2
#define TT      2048
#define M_TOT   (BB * TT)      // 4096
#define D_FF    (4 * D_MODEL)  // 4096

// ---------------------------------------------------------------------------
// Scratch (static __device__ arrays; no allocation allowed)
// ---------------------------------------------------------------------------
__device__ float g_x[M_TOT * D_MODEL];     // 16 MB  residual stream
__device__ float g_q[M_TOT * D_MODEL];     // 16 MB
__device__ float g_k[M_TOT * D_MODEL];     // 16 MB
__device__ float g_v[M_TOT * D_MODEL];     // 16 MB
__device__ float g_s[BB * TT * TT];        // 32 MB  scores / attn (in-place)
__device__ float g_h[M_TOT * D_FF];        // 64 MB  MLP hidden

// ---------------------------------------------------------------------------
// Embedding: x[b,t,:] = tok_emb[idx[b,t],:] + pos_emb[t,:]
// ---------------------------------------------------------------------------
__global__ void embed_kernel(const int* __restrict__ idx,
                             const float* __restrict__ tok,
                             const float* __restrict__ pos) {
    int i = blockIdx.x * blockDim.x + threadIdx.x;
    int n4 = (M_TOT * D_MODEL) / 4;
    if (i >= n4) return;
    int e   = i * 4;
    int row = e / D_MODEL;
    int d   = e % D_MODEL;
    int t   = row % TT;
    int tk  = idx[row];
    const float4 a = *reinterpret_cast<const float4*>(tok + (long)tk * D_MODEL + d);
    const float4 b = *reinterpret_cast<const float4*>(pos + (long)t  * D_MODEL + d);
    float4 o;
    o.x = a.x + b.x; o.y = a.y + b.y; o.z = a.z + b.z; o.w = a.w + b.w;
    *reinterpret_cast<float4*>(g_x + e) = o;
}

// ---------------------------------------------------------------------------
// TF32 tensor-core GEMM: C = epi(alpha * A @ B(^T) [+bias]) [res + rs*(...)]
//   A: [M,K] row-major.  B: [K,N] row-major, or [N,K] row-major if TRANSB.
//   Block tile 128x128x32, 256 threads = 8 warps (2 m x 4 n), warp 64x32.
//   wmma 16x16x8 tf32 -> fp32 accum.
//   Requires: M,N % 128 == 0, K % 32 == 0  (true at every call site).
// ---------------------------------------------------------------------------
template<bool TRANSB, bool HAS_BIAS, bool DO_GELU, bool HAS_RES>
__global__ __launch_bounds__(256)
void tgemm(const float* __restrict__ A, const float* __restrict__ Bm,
           const float* __restrict__ bias, const float* __restrict__ Res,
           float* __restrict__ C, int M, int N, int K,
           float alpha, float res_scale,
           long sA, long sB, long sC, long sR)
{
    constexpr int BM = 128, BN = 128, BK = 32;
    constexpr int LDA = BK + 4;                      // 36, keeps 16B alignment
    constexpr int LDB_NT = BN + 4;                   // 132
    constexpr int LDB_T  = BK + 4;                   // 36

    A  += (long)blockIdx.z * sA;
    Bm += (long)blockIdx.z * sB;
    C  += (long)blockIdx.z * sC;
    if (HAS_RES) Res += (long)blockIdx.z * sR;

    __shared__ float As[BM][LDA];
    __shared__ float Bs[TRANSB ? BM : BK][TRANSB ? LDB_T : LDB_NT];
    __shared__ float stg[8][16][20];

    const int tid  = threadIdx.x;
    const int wid  = tid / 32;
    const int lane = tid % 32;
    const int warp_m = wid % 2;      // 0..1  -> 64-row slab
    const int warp_n = wid / 2;      // 0..3  -> 32-col slab
    const int cRow = blockIdx.y * BM;
    const int cCol = blockIdx.x * BN;

    wmma::fragment<wmma::accumulator, 16, 16, 8, float> acc[4][2];
#pragma unroll
    for (int mt = 0; mt < 4; mt++)
#pragma unroll
        for (int nt = 0; nt < 2; nt++)
            wmma::fill_fragment(acc[mt][nt], 0.0f);

    for (int kt = 0; kt < K; kt += BK) {
        // ---- load A tile: rows cRow..+127, cols kt..+31 (8 float4 per row)
#pragma unroll
        for (int i = 0; i < 4; i++) {
            int f = tid + i * 256;          // 0..1023
            int r = f >> 3;                 // 0..127
            int c = (f & 7) * 4;            // 0,4,...,28
            float4 v = *reinterpret_cast<const float4*>(A + (long)(cRow + r) * K + kt + c);
            *reinterpret_cast<float4*>(&As[r][c]) = v;
        }
        // ---- load B tile
        if (!TRANSB) {
#pragma unroll
            for (int i = 0; i < 4; i++) {
                int f = tid + i * 256;
                int r = f >> 5;             // 0..31
                int c = (f & 31) * 4;       // 0..124
                float4 v = *reinterpret_cast<const float4*>(Bm + (long)(kt + r) * N + cCol + c);
                *reinterpret_cast<float4*>(&Bs[r][c]) = v;
            }
        } else {
#pragma unroll
            for (int i = 0; i < 4; i++) {
                int f = tid + i * 256;
                int r = f >> 3;             // 0..127 (n index)
                int c = (f & 7) * 4;        // 0..28  (k index)
                float4 v = *reinterpret_cast<const float4*>(Bm + (long)(cCol + r) * K + kt + c);
                *reinterpret_cast<float4*>(&Bs[r][c]) = v;
            }
        }
        __syncthreads();

        // ---- MMA over the 4 k-steps of this tile
#pragma unroll
        for (int kk = 0; kk < BK; kk += 8) {
            wmma::fragment<wmma::matrix_a, 16, 16, 8, wmma::precision::tf32, wmma::row_major> af[4];
#pragma unroll
            for (int mt = 0; mt < 4; mt++) {
                wmma::load_matrix_sync(af[mt], &As[warp_m * 64 + mt * 16][kk], LDA);
#pragma unroll
                for (int e = 0; e < af[mt].num_elements; e++)
                    af[mt].x[e] = wmma::__float_to_tf32(af[mt].x[e]);
            }
            if (!TRANSB) {
                wmma::fragment<wmma::matrix_b, 16, 16, 8, wmma::precision::tf32, wmma::row_major> bf[2];
#pragma unroll
                for (int nt = 0; nt < 2; nt++) {
                    wmma::load_matrix_sync(bf[nt], &Bs[kk][warp_n * 32 + nt * 16], LDB_NT);
#pragma unroll
                    for (int e = 0; e < bf[nt].num_elements; e++)
                        bf[nt].x[e] = wmma::__float_to_tf32(bf[nt].x[e]);
                }
#pragma unroll
                for (int mt = 0; mt < 4; mt++)
#pragma unroll
                    for (int nt = 0; nt < 2; nt++)
                        wmma::mma_sync(acc[mt][nt], af[mt], bf[nt], acc[mt][nt]);
            } else {
                wmma::fragment<wmma::matrix_b, 16, 16, 8, wmma::precision::tf32, wmma::col_major> bf[2];
#pragma unroll
                for (int nt = 0; nt < 2; nt++) {
                    wmma::load_matrix_sync(bf[nt], &Bs[warp_n * 32 + nt * 16][kk], LDB_T);
#pragma unroll
                    for (int e = 0; e < bf[nt].num_elements; e++)
                        bf[nt].x[e] = wmma::__float_to_tf32(bf[nt].x[e]);
                }
#pragma unroll
                for (int mt = 0; mt < 4; mt++)
#pragma unroll
                    for (int nt = 0; nt < 2; nt++)
                        wmma::mma_sync(acc[mt][nt], af[mt], bf[nt], acc[mt][nt]);
            }
        }
        __syncthreads();
    }

    // ---- fused epilogue via per-warp smem staging
    const int er = lane >> 1;            // 0..15
    const int ec0 = (lane & 1) * 8;      // 0 or 8
#pragma unroll
    for (int mt = 0; mt < 4; mt++) {
#pragma unroll
        for (int nt = 0; nt < 2; nt++) {
#pragma unroll
            for (int e = 0; e < acc[mt][nt].num_elements; e++)
                acc[mt][nt].x[e] *= alpha;
            wmma::store_matrix_sync(&stg[wid][0][0], acc[mt][nt], 20, wmma::mem_row_major);
            __syncwarp();
            long grow = cRow + warp_m * 64 + mt * 16 + er;
            long gcol = cCol + warp_n * 32 + nt * 16 + ec0;
#pragma unroll
            for (int j = 0; j < 8; j++) {
                float v = stg[wid][er][ec0 + j];
                if (HAS_BIAS) v += bias[gcol + j];
                if (DO_GELU)  v = 0.5f * v * (1.0f + erff(v * 0.70710678118f));
                if (HAS_RES)  v = Res[grow * N + gcol + j] + res_scale * v;
                C[grow * N + gcol + j] = v;
            }
            __syncwarp();
        }
    }
}

// ---------------------------------------------------------------------------
// Causal row softmax, in place on g_s. One block per (b,q) row.
// ---------------------------------------------------------------------------
__global__ void softmax_causal(float* __restrict__ s) {
    const int row = blockIdx.x;           // b*TT + q
    const int q   = row % TT;
    float* p = s + (long)row * TT;
    const int n = q + 1;
    const int tid = threadIdx.x;
    __shared__ float red[256];

    float m = -INFINITY;
    for (int j = tid; j < n; j += 256) m = fmaxf(m, p[j]);
    red[tid] = m; __syncthreads();
    for (int st = 128; st > 0; st >>= 1) {
        if (tid < st) red[tid] = fmaxf(red[tid], red[tid + st]);
        __syncthreads();
    }
    m = red[0]; __syncthreads();

    float sum = 0.f;
    for (int j = tid; j < n; j += 256) {
        float e = __expf(p[j] - m);
        p[j] = e;
        sum += e;
    }
    red[tid] = sum; __syncthreads();
    for (int st = 128; st > 0; st >>= 1) {
        if (tid < st) red[tid] += red[tid + st];
        __syncthreads();
    }
    const float inv = 1.0f / red[0];
    __syncthreads();

    for (int j = tid; j < n; j += 256) p[j] *= inv;
    for (int j = n + tid; j < TT; j += 256) p[j] = 0.f;
}

// ---------------------------------------------------------------------------
// Launch
// ---------------------------------------------------------------------------
extern "C" void kernel_launch(void* const* d_in, const int* in_sizes, int n_in,
                              void* d_out, int out_size) {
    const int*   idx  = (const int*)d_in[0];
    const float* tok  = (const float*)d_in[1];
    const float* pos  = (const float*)d_in[2];
    const float* Wq   = (const float*)d_in[3];
    const float* Wk   = (const float*)d_in[4];
    const float* Wv   = (const float*)d_in[5];
    const float* W1   = (const float*)d_in[6];
    const float* b1   = (const float*)d_in[7];
    const float* W2   = (const float*)d_in[8];
    const float* b2   = (const float*)d_in[9];
    const float* Wout = (const float*)d_in[10];
    const float* bout = (const float*)d_in[11];
    float* out = (float*)d_out;

    float *x, *q, *k, *v, *s, *h;
    cudaGetSymbolAddress((void**)&x, g_x);
    cudaGetSymbolAddress((void**)&q, g_q);
    cudaGetSymbolAddress((void**)&k, g_k);
    cudaGetSymbolAddress((void**)&v, g_v);
    cudaGetSymbolAddress((void**)&s, g_s);
    cudaGetSymbolAddress((void**)&h, g_h);

    // 1. embeddings -> g_x
    {
        int n4 = (M_TOT * D_MODEL) / 4;
        embed_kernel<<<(n4 + 255) / 256, 256>>>(idx, tok, pos);
    }

    // 2. q,k,v = x @ W{q,k,v}
    {
        dim3 grid(D_MODEL / 128, M_TOT / 128, 1);
        tgemm<false,false,false,false><<<grid, 256>>>(x, Wq, nullptr, nullptr, q,
            M_TOT, D_MODEL, D_MODEL, 1.0f, 0.f, 0, 0, 0, 0);
        tgemm<false,false,false,false><<<grid, 256>>>(x, Wk, nullptr, nullptr, k,
            M_TOT, D_MODEL, D_MODEL, 1.0f, 0.f, 0, 0, 0, 0);
        tgemm<false,false,false,false><<<grid, 256>>>(x, Wv, nullptr, nullptr, v,
            M_TOT, D_MODEL, D_MODEL, 1.0f, 0.f, 0, 0, 0, 0);
    }

    // 3. scores = (q @ k^T) / 32   per batch
    {
        dim3 grid(TT / 128, TT / 128, BB);
        tgemm<true,false,false,false><<<grid, 256>>>(q, k, nullptr, nullptr, s,
            TT, TT, D_MODEL, 1.0f / 32.0f, 0.f,
            (long)TT * D_MODEL, (long)TT * D_MODEL, (long)TT * TT, 0);
    }

    // 4. causal softmax (in place)
    softmax_causal<<<BB * TT, 256>>>(s);

    // 5. x = x + 0.125 * (attn @ v)  per batch
    {
        dim3 grid(D_MODEL / 128, TT / 128, BB);
        tgemm<false,false,false,true><<<grid, 256>>>(s, v, nullptr, x, x,
            TT, D_MODEL, TT, 1.0f, 0.125f,
            (long)TT * TT, (long)TT * D_MODEL, (long)TT * D_MODEL, (long)TT * D_MODEL);
    }

    // 6. h = gelu(x @ W1 + b1)
    {
        dim3 grid(D_FF / 128, M_TOT / 128, 1);
        tgemm<false,true,true,false><<<grid, 256>>>(x, W1, b1, nullptr, h,
            M_TOT, D_FF, D_MODEL, 1.0f, 0.f, 0, 0, 0, 0);
    }

    // 7. x = x + (h @ W2 + b2)
    {
        dim3 grid(D_MODEL / 128, M_TOT / 128, 1);
        tgemm<false,true,false,true><<<grid, 256>>>(h, W2, b2, x, x,
            M_TOT, D_MODEL, D_FF, 1.0f, 1.0f, 0, 0, 0, 0);
    }

    // 8. out = x @ Wout + bout
    {
        dim3 grid(VOCAB / 128, M_TOT / 128, 1);
        tgemm<false,true,false,false><<<grid, 256>>>(x, Wout, bout, nullptr, out,
            M_TOT, VOCAB, D_MODEL, 1.0f, 0.f, 0, 0, 0, 0);
    }
}

// round 4
// speedup vs baseline: 1.8635x; 1.2770x over previous
#include <cuda_runtime.h>
#include <mma.h>
#include <math.h>

using namespace nvcuda;

#define D_MODEL 1024
#define VOCAB   32000
#define BB      2
#define TT      2048
#define M_TOT   (BB * TT)      // 4096
#define D_FF    (4 * D_MODEL)  // 4096

// ---------------------------------------------------------------------------
// Scratch
// ---------------------------------------------------------------------------
__device__ float g_x[M_TOT * D_MODEL];
__device__ float g_q[M_TOT * D_MODEL];
__device__ float g_k[M_TOT * D_MODEL];
__device__ float g_v[M_TOT * D_MODEL];
__device__ float g_s[BB * TT * TT];
__device__ float g_h[M_TOT * D_FF];

// ---------------------------------------------------------------------------
// cp.async helpers
// ---------------------------------------------------------------------------
__device__ __forceinline__ void cp_async16(void* dst, const float* src) {
    unsigned d = (unsigned)__cvta_generic_to_shared(dst);
    asm volatile("cp.async.ca.shared.global [%0], [%1], 16;\n" :: "r"(d), "l"(src));
}
__device__ __forceinline__ void cp_commit() { asm volatile("cp.async.commit_group;\n"); }
__device__ __forceinline__ void cp_wait1()  { asm volatile("cp.async.wait_group 1;\n"); }

// ---------------------------------------------------------------------------
// Embedding
// ---------------------------------------------------------------------------
__global__ void embed_kernel(const int* __restrict__ idx,
                             const float* __restrict__ tok,
                             const float* __restrict__ pos) {
    int i = blockIdx.x * blockDim.x + threadIdx.x;
    int n4 = (M_TOT * D_MODEL) / 4;
    if (i >= n4) return;
    int e   = i * 4;
    int row = e / D_MODEL;
    int d   = e % D_MODEL;
    int t   = row % TT;
    int tk  = idx[row];
    const float4 a = *reinterpret_cast<const float4*>(tok + (long)tk * D_MODEL + d);
    const float4 b = *reinterpret_cast<const float4*>(pos + (long)t  * D_MODEL + d);
    float4 o;
    o.x = a.x + b.x; o.y = a.y + b.y; o.z = a.z + b.z; o.w = a.w + b.w;
    *reinterpret_cast<float4*>(g_x + e) = o;
}

// ---------------------------------------------------------------------------
// TF32 tensor GEMM, cp.async double-buffered.
//   C = epi(alpha * A @ B(^T) [+bias]) [res + rs*(...)]
//   Block 128x128x32, 8 warps (2m x 4n), warp 64x32, wmma 16x16x8 tf32.
//   CAUSAL: skip tiles strictly above the diagonal (output never read there).
//   KCAP:   truncate K to cRow+BM (A cols beyond are zero: causal attn rows).
// ---------------------------------------------------------------------------
template<bool TRANSB, bool HAS_BIAS, bool DO_GELU, bool HAS_RES, bool CAUSAL, bool KCAP>
__global__ __launch_bounds__(256, 2)
void tgemm(const float* __restrict__ A, const float* __restrict__ Bm,
           const float* __restrict__ bias, const float* __restrict__ Res,
           float* __restrict__ C, int M, int N, int K,
           float alpha, float res_scale,
           long sA, long sB, long sC, long sR)
{
    constexpr int BM = 128, BN = 128, BK = 32;
    constexpr int LDA   = 36;
    constexpr int LDB   = TRANSB ? 36 : 132;
    constexpr int BROWS = TRANSB ? BM : BK;

    if (CAUSAL && blockIdx.x > blockIdx.y) return;

    A  += (long)blockIdx.z * sA;
    Bm += (long)blockIdx.z * sB;
    C  += (long)blockIdx.z * sC;
    if (HAS_RES) Res += (long)blockIdx.z * sR;

    __shared__ float As[2][BM][LDA];
    __shared__ float Bs[2][BROWS][LDB];
    __shared__ float stg[8][16][20];

    const int tid  = threadIdx.x;
    const int wid  = tid / 32;
    const int lane = tid % 32;
    const int warp_m = wid % 2;
    const int warp_n = wid / 2;
    const int cRow = blockIdx.y * BM;
    const int cCol = blockIdx.x * BN;

    const int Keff = KCAP ? (K < cRow + BM ? K : cRow + BM) : K;
    const int nT = Keff / BK;

    // load coordinates
    const int a_r0 = tid >> 3;          // 0..31, +32 per rep (4 reps -> 128 rows)
    const int a_c  = (tid & 7) * 4;     // 0..28
    const int b_r0 = tid >> 5;          // 0..7,  +8 per rep  (4 reps -> 32 rows)
    const int b_c  = (tid & 31) * 4;    // 0..124

    const float* Abase = A + (long)cRow * K + a_c;

    // ---- prologue: stage tile 0 into buf 0
    {
        const float* ap = Abase;
#pragma unroll
        for (int i = 0; i < 4; i++)
            cp_async16(&As[0][a_r0 + 32 * i][a_c], ap + (long)(a_r0 + 32 * i) * K);
        if (!TRANSB) {
#pragma unroll
            for (int i = 0; i < 4; i++)
                cp_async16(&Bs[0][b_r0 + 8 * i][b_c], Bm + (long)(b_r0 + 8 * i) * N + cCol + b_c);
        } else {
#pragma unroll
            for (int i = 0; i < 4; i++)
                cp_async16(&Bs[0][a_r0 + 32 * i][a_c], Bm + (long)(cCol + a_r0 + 32 * i) * K + a_c);
        }
        cp_commit();
    }

    wmma::fragment<wmma::accumulator, 16, 16, 8, float> acc[4][2];
#pragma unroll
    for (int mt = 0; mt < 4; mt++)
#pragma unroll
        for (int nt = 0; nt < 2; nt++)
            wmma::fill_fragment(acc[mt][nt], 0.0f);

    for (int t = 0; t < nT; t++) {
        // ---- stage tile t+1 into the other buffer
        if (t + 1 < nT) {
            const int kt = (t + 1) * BK;
            const int nb = (t + 1) & 1;
#pragma unroll
            for (int i = 0; i < 4; i++)
                cp_async16(&As[nb][a_r0 + 32 * i][a_c], Abase + kt + (long)(a_r0 + 32 * i) * K);
            if (!TRANSB) {
#pragma unroll
                for (int i = 0; i < 4; i++)
                    cp_async16(&Bs[nb][b_r0 + 8 * i][b_c], Bm + (long)(kt + b_r0 + 8 * i) * N + cCol + b_c);
            } else {
#pragma unroll
                for (int i = 0; i < 4; i++)
                    cp_async16(&Bs[nb][a_r0 + 32 * i][a_c], Bm + (long)(cCol + a_r0 + 32 * i) * K + kt + a_c);
            }
        }
        cp_commit();
        cp_wait1();                 // buffer t is complete
        __syncthreads();

        const int cb = t & 1;
#pragma unroll
        for (int kk = 0; kk < BK; kk += 8) {
            wmma::fragment<wmma::matrix_a, 16, 16, 8, wmma::precision::tf32, wmma::row_major> af[4];
#pragma unroll
            for (int mt = 0; mt < 4; mt++) {
                wmma::load_matrix_sync(af[mt], &As[cb][warp_m * 64 + mt * 16][kk], LDA);
#pragma unroll
                for (int e = 0; e < af[mt].num_elements; e++)
                    af[mt].x[e] = wmma::__float_to_tf32(af[mt].x[e]);
            }
            if (!TRANSB) {
                wmma::fragment<wmma::matrix_b, 16, 16, 8, wmma::precision::tf32, wmma::row_major> bf[2];
#pragma unroll
                for (int nt = 0; nt < 2; nt++) {
                    wmma::load_matrix_sync(bf[nt], &Bs[cb][kk][warp_n * 32 + nt * 16], LDB);
#pragma unroll
                    for (int e = 0; e < bf[nt].num_elements; e++)
                        bf[nt].x[e] = wmma::__float_to_tf32(bf[nt].x[e]);
                }
#pragma unroll
                for (int mt = 0; mt < 4; mt++)
#pragma unroll
                    for (int nt = 0; nt < 2; nt++)
                        wmma::mma_sync(acc[mt][nt], af[mt], bf[nt], acc[mt][nt]);
            } else {
                wmma::fragment<wmma::matrix_b, 16, 16, 8, wmma::precision::tf32, wmma::col_major> bf[2];
#pragma unroll
                for (int nt = 0; nt < 2; nt++) {
                    wmma::load_matrix_sync(bf[nt], &Bs[cb][warp_n * 32 + nt * 16][kk], LDB);
#pragma unroll
                    for (int e = 0; e < bf[nt].num_elements; e++)
                        bf[nt].x[e] = wmma::__float_to_tf32(bf[nt].x[e]);
                }
#pragma unroll
                for (int mt = 0; mt < 4; mt++)
#pragma unroll
                    for (int nt = 0; nt < 2; nt++)
                        wmma::mma_sync(acc[mt][nt], af[mt], bf[nt], acc[mt][nt]);
            }
        }
        __syncthreads();            // MMA done before next iter overwrites buf
    }

    // ---- fused epilogue via per-warp smem staging
    const int er  = lane >> 1;
    const int ec0 = (lane & 1) * 8;
#pragma unroll
    for (int mt = 0; mt < 4; mt++) {
#pragma unroll
        for (int nt = 0; nt < 2; nt++) {
#pragma unroll
            for (int e = 0; e < acc[mt][nt].num_elements; e++)
                acc[mt][nt].x[e] *= alpha;
            wmma::store_matrix_sync(&stg[wid][0][0], acc[mt][nt], 20, wmma::mem_row_major);
            __syncwarp();
            long grow = cRow + warp_m * 64 + mt * 16 + er;
            long gcol = cCol + warp_n * 32 + nt * 16 + ec0;
#pragma unroll
            for (int j = 0; j < 8; j++) {
                float v = stg[wid][er][ec0 + j];
                if (HAS_BIAS) v += bias[gcol + j];
                if (DO_GELU)  v = 0.5f * v * (1.0f + erff(v * 0.70710678118f));
                if (HAS_RES)  v = Res[grow * N + gcol + j] + res_scale * v;
                C[grow * N + gcol + j] = v;
            }
            __syncwarp();
        }
    }
}

// ---------------------------------------------------------------------------
// Causal row softmax, in place on g_s.
// ---------------------------------------------------------------------------
__global__ void softmax_causal(float* __restrict__ s) {
    const int row = blockIdx.x;
    const int q   = row % TT;
    float* p = s + (long)row * TT;
    const int n = q + 1;
    const int tid = threadIdx.x;
    __shared__ float red[256];

    float m = -INFINITY;
    for (int j = tid; j < n; j += 256) m = fmaxf(m, p[j]);
    red[tid] = m; __syncthreads();
    for (int st = 128; st > 0; st >>= 1) {
        if (tid < st) red[tid] = fmaxf(red[tid], red[tid + st]);
        __syncthreads();
    }
    m = red[0]; __syncthreads();

    float sum = 0.f;
    for (int j = tid; j < n; j += 256) {
        float e = __expf(p[j] - m);
        p[j] = e;
        sum += e;
    }
    red[tid] = sum; __syncthreads();
    for (int st = 128; st > 0; st >>= 1) {
        if (tid < st) red[tid] += red[tid + st];
        __syncthreads();
    }
    const float inv = 1.0f / red[0];
    __syncthreads();

    for (int j = tid; j < n; j += 256) p[j] *= inv;
    for (int j = n + tid; j < TT; j += 256) p[j] = 0.f;
}

// ---------------------------------------------------------------------------
// Launch
// ---------------------------------------------------------------------------
extern "C" void kernel_launch(void* const* d_in, const int* in_sizes, int n_in,
                              void* d_out, int out_size) {
    const int*   idx  = (const int*)d_in[0];
    const float* tok  = (const float*)d_in[1];
    const float* pos  = (const float*)d_in[2];
    const float* Wq   = (const float*)d_in[3];
    const float* Wk   = (const float*)d_in[4];
    const float* Wv   = (const float*)d_in[5];
    const float* W1   = (const float*)d_in[6];
    const float* b1   = (const float*)d_in[7];
    const float* W2   = (const float*)d_in[8];
    const float* b2   = (const float*)d_in[9];
    const float* Wout = (const float*)d_in[10];
    const float* bout = (const float*)d_in[11];
    float* out = (float*)d_out;

    float *x, *q, *k, *v, *s, *h;
    cudaGetSymbolAddress((void**)&x, g_x);
    cudaGetSymbolAddress((void**)&q, g_q);
    cudaGetSymbolAddress((void**)&k, g_k);
    cudaGetSymbolAddress((void**)&v, g_v);
    cudaGetSymbolAddress((void**)&s, g_s);
    cudaGetSymbolAddress((void**)&h, g_h);

    // 1. embeddings
    {
        int n4 = (M_TOT * D_MODEL) / 4;
        embed_kernel<<<(n4 + 255) / 256, 256>>>(idx, tok, pos);
    }

    // 2. q,k,v = x @ W{q,k,v}
    {
        dim3 grid(D_MODEL / 128, M_TOT / 128, 1);
        tgemm<false,false,false,false,false,false><<<grid, 256>>>(x, Wq, nullptr, nullptr, q,
            M_TOT, D_MODEL, D_MODEL, 1.0f, 0.f, 0, 0, 0, 0);
        tgemm<false,false,false,false,false,false><<<grid, 256>>>(x, Wk, nullptr, nullptr, k,
            M_TOT, D_MODEL, D_MODEL, 1.0f, 0.f, 0, 0, 0, 0);
        tgemm<false,false,false,false,false,false><<<grid, 256>>>(x, Wv, nullptr, nullptr, v,
            M_TOT, D_MODEL, D_MODEL, 1.0f, 0.f, 0, 0, 0, 0);
    }

    // 3. scores = (q @ k^T) / 32, lower-triangle tiles only
    {
        dim3 grid(TT / 128, TT / 128, BB);
        tgemm<true,false,false,false,true,false><<<grid, 256>>>(q, k, nullptr, nullptr, s,
            TT, TT, D_MODEL, 1.0f / 32.0f, 0.f,
            (long)TT * D_MODEL, (long)TT * D_MODEL, (long)TT * TT, 0);
    }

    // 4. causal softmax
    softmax_causal<<<BB * TT, 256>>>(s);

    // 5. x = x + 0.125 * (attn @ v), K capped at cRow+128
    {
        dim3 grid(D_MODEL / 128, TT / 128, BB);
        tgemm<false,false,false,true,false,true><<<grid, 256>>>(s, v, nullptr, x, x,
            TT, D_MODEL, TT, 1.0f, 0.125f,
            (long)TT * TT, (long)TT * D_MODEL, (long)TT * D_MODEL, (long)TT * D_MODEL);
    }

    // 6. h = gelu(x @ W1 + b1)
    {
        dim3 grid(D_FF / 128, M_TOT / 128, 1);
        tgemm<false,true,true,false,false,false><<<grid, 256>>>(x, W1, b1, nullptr, h,
            M_TOT, D_FF, D_MODEL, 1.0f, 0.f, 0, 0, 0, 0);
    }

    // 7. x = x + (h @ W2 + b2)
    {
        dim3 grid(D_MODEL / 128, M_TOT / 128, 1);
        tgemm<false,true,false,true,false,false><<<grid, 256>>>(h, W2, b2, x, x,
            M_TOT, D_MODEL, D_FF, 1.0f, 1.0f, 0, 0, 0, 0);
    }

    // 8. out = x @ Wout + bout
    {
        dim3 grid(VOCAB / 128, M_TOT / 128, 1);
        tgemm<false,true,false,false,false,false><<<grid, 256>>>(x, Wout, bout, nullptr, out,
            M_TOT, VOCAB, D_MODEL, 1.0f, 0.f, 0, 0, 0, 0);
    }
}

// round 7
// speedup vs baseline: 1.9616x; 1.0526x over previous
#include <cuda_runtime.h>
#include <mma.h>
#include <math.h>

using namespace nvcuda;

#define D_MODEL 1024
#define VOCAB   32000
#define BB      2
#define TT      2048
#define M_TOT   (BB * TT)      // 4096
#define D_FF    (4 * D_MODEL)  // 4096

// ---------------------------------------------------------------------------
// Scratch (static device arrays)
// ---------------------------------------------------------------------------
__device__ float g_x [M_TOT * D_MODEL];    // residual stream (fp32)
__device__ float g_xt[M_TOT * D_MODEL];    // tf32-rounded copy of x (GEMM A)
__device__ float g_q [M_TOT * D_MODEL];    // tf32-rounded
__device__ float g_k [M_TOT * D_MODEL];    // tf32-rounded
__device__ float g_v [M_TOT * D_MODEL];    // tf32-rounded
__device__ float g_s [BB * TT * TT];       // scores / attn (attn tf32-rounded)
__device__ float g_h [M_TOT * D_FF];       // MLP hidden (tf32-rounded)
// tf32-rounded weights
__device__ float g_wq[D_MODEL * D_MODEL];
__device__ float g_wk[D_MODEL * D_MODEL];
__device__ float g_wv[D_MODEL * D_MODEL];
__device__ float g_w1[D_MODEL * D_FF];
__device__ float g_w2[D_FF * D_MODEL];
__device__ float g_wo[D_MODEL * VOCAB];

// ---------------------------------------------------------------------------
// helpers
// ---------------------------------------------------------------------------
__device__ __forceinline__ float rtf(float v) { return wmma::__float_to_tf32(v); }

__device__ __forceinline__ void cp_async16(void* dst, const float* src) {
    unsigned d = (unsigned)__cvta_generic_to_shared(dst);
    asm volatile("cp.async.ca.shared.global [%0], [%1], 16;\n" :: "r"(d), "l"(src));
}
__device__ __forceinline__ void cp_commit() { asm volatile("cp.async.commit_group;\n"); }
__device__ __forceinline__ void cp_wait1()  { asm volatile("cp.async.wait_group 1;\n"); }

// ---------------------------------------------------------------------------
// Weight rounding prepass: out = tf32_round(in), vectorized
// ---------------------------------------------------------------------------
__global__ void round_tf32_kernel(const float* __restrict__ in,
                                  float* __restrict__ out, int n4) {
    int i = blockIdx.x * blockDim.x + threadIdx.x;
    if (i >= n4) return;
    float4 v = reinterpret_cast<const float4*>(in)[i];
    v.x = rtf(v.x); v.y = rtf(v.y); v.z = rtf(v.z); v.w = rtf(v.w);
    reinterpret_cast<float4*>(out)[i] = v;
}

// ---------------------------------------------------------------------------
// Embedding: x = tok[idx] + pos ; also writes tf32-rounded copy
// ---------------------------------------------------------------------------
__global__ void embed_kernel(const int* __restrict__ idx,
                             const float* __restrict__ tok,
                             const float* __restrict__ pos) {
    int i = blockIdx.x * blockDim.x + threadIdx.x;
    int n4 = (M_TOT * D_MODEL) / 4;
    if (i >= n4) return;
    int e   = i * 4;
    int row = e / D_MODEL;
    int d   = e % D_MODEL;
    int t   = row % TT;
    int tk  = idx[row];
    const float4 a = *reinterpret_cast<const float4*>(tok + (long)tk * D_MODEL + d);
    const float4 b = *reinterpret_cast<const float4*>(pos + (long)t  * D_MODEL + d);
    float4 o;
    o.x = a.x + b.x; o.y = a.y + b.y; o.z = a.z + b.z; o.w = a.w + b.w;
    *reinterpret_cast<float4*>(g_x + e) = o;
    float4 r;
    r.x = rtf(o.x); r.y = rtf(o.y); r.z = rtf(o.z); r.w = rtf(o.w);
    *reinterpret_cast<float4*>(g_xt + e) = r;
}

// ---------------------------------------------------------------------------
// TF32 tensor GEMM, cp.async double-buffered, NO in-loop conversions
// (all operands are pre-rounded to tf32 bit patterns).
//   C = epi(alpha * A @ B(^T) [+bias])  [res + rs*(...)]
//   ROUND_OUT: round stored value to tf32.
//   DUAL_OUT:  C gets fp32, C2 gets tf32-rounded copy.
// ---------------------------------------------------------------------------
template<bool TRANSB, bool HAS_BIAS, bool DO_GELU, bool HAS_RES,
         bool CAUSAL, bool KCAP, bool ROUND_OUT, bool DUAL_OUT>
__global__ __launch_bounds__(256, 2)
void tgemm(const float* __restrict__ A, const float* __restrict__ Bm,
           const float* __restrict__ bias, const float* __restrict__ Res,
           float* __restrict__ C, float* __restrict__ C2,
           int M, int N, int K,
           float alpha, float res_scale,
           long sA, long sB, long sC, long sR)
{
    constexpr int BM = 128, BN = 128, BK = 32;
    constexpr int LDA   = 36;
    constexpr int LDB   = TRANSB ? 36 : 132;
    constexpr int BROWS = TRANSB ? BM : BK;

    if (CAUSAL && blockIdx.x > blockIdx.y) return;

    A  += (long)blockIdx.z * sA;
    Bm += (long)blockIdx.z * sB;
    C  += (long)blockIdx.z * sC;
    if (DUAL_OUT) C2 += (long)blockIdx.z * sC;
    if (HAS_RES)  Res += (long)blockIdx.z * sR;

    __shared__ float As[2][BM][LDA];
    __shared__ float Bs[2][BROWS][LDB];
    __shared__ float stg[8][16][20];

    const int tid  = threadIdx.x;
    const int wid  = tid / 32;
    const int lane = tid % 32;
    const int warp_m = wid % 2;
    const int warp_n = wid / 2;
    const int cRow = blockIdx.y * BM;
    const int cCol = blockIdx.x * BN;

    const int Keff = KCAP ? (K < cRow + BM ? K : cRow + BM) : K;
    const int nT = Keff / BK;

    const int a_r0 = tid >> 3;
    const int a_c  = (tid & 7) * 4;
    const int b_r0 = tid >> 5;
    const int b_c  = (tid & 31) * 4;

    const float* Abase = A + (long)cRow * K + a_c;

    {
#pragma unroll
        for (int i = 0; i < 4; i++)
            cp_async16(&As[0][a_r0 + 32 * i][a_c], Abase + (long)(a_r0 + 32 * i) * K);
        if (!TRANSB) {
#pragma unroll
            for (int i = 0; i < 4; i++)
                cp_async16(&Bs[0][b_r0 + 8 * i][b_c], Bm + (long)(b_r0 + 8 * i) * N + cCol + b_c);
        } else {
#pragma unroll
            for (int i = 0; i < 4; i++)
                cp_async16(&Bs[0][a_r0 + 32 * i][a_c], Bm + (long)(cCol + a_r0 + 32 * i) * K + a_c);
        }
        cp_commit();
    }

    wmma::fragment<wmma::accumulator, 16, 16, 8, float> acc[4][2];
#pragma unroll
    for (int mt = 0; mt < 4; mt++)
#pragma unroll
        for (int nt = 0; nt < 2; nt++)
            wmma::fill_fragment(acc[mt][nt], 0.0f);

    for (int t = 0; t < nT; t++) {
        if (t + 1 < nT) {
            const int kt = (t + 1) * BK;
            const int nb = (t + 1) & 1;
#pragma unroll
            for (int i = 0; i < 4; i++)
                cp_async16(&As[nb][a_r0 + 32 * i][a_c], Abase + kt + (long)(a_r0 + 32 * i) * K);
            if (!TRANSB) {
#pragma unroll
                for (int i = 0; i < 4; i++)
                    cp_async16(&Bs[nb][b_r0 + 8 * i][b_c], Bm + (long)(kt + b_r0 + 8 * i) * N + cCol + b_c);
            } else {
#pragma unroll
                for (int i = 0; i < 4; i++)
                    cp_async16(&Bs[nb][a_r0 + 32 * i][a_c], Bm + (long)(cCol + a_r0 + 32 * i) * K + kt + a_c);
            }
        }
        cp_commit();
        cp_wait1();
        __syncthreads();

        const int cb = t & 1;
#pragma unroll
        for (int kk = 0; kk < BK; kk += 8) {
            wmma::fragment<wmma::matrix_a, 16, 16, 8, wmma::precision::tf32, wmma::row_major> af[4];
#pragma unroll
            for (int mt = 0; mt < 4; mt++)
                wmma::load_matrix_sync(af[mt], &As[cb][warp_m * 64 + mt * 16][kk], LDA);
            if (!TRANSB) {
                wmma::fragment<wmma::matrix_b, 16, 16, 8, wmma::precision::tf32, wmma::row_major> bf[2];
#pragma unroll
                for (int nt = 0; nt < 2; nt++)
                    wmma::load_matrix_sync(bf[nt], &Bs[cb][kk][warp_n * 32 + nt * 16], LDB);
#pragma unroll
                for (int mt = 0; mt < 4; mt++)
#pragma unroll
                    for (int nt = 0; nt < 2; nt++)
                        wmma::mma_sync(acc[mt][nt], af[mt], bf[nt], acc[mt][nt]);
            } else {
                wmma::fragment<wmma::matrix_b, 16, 16, 8, wmma::precision::tf32, wmma::col_major> bf[2];
#pragma unroll
                for (int nt = 0; nt < 2; nt++)
                    wmma::load_matrix_sync(bf[nt], &Bs[cb][warp_n * 32 + nt * 16][kk], LDB);
#pragma unroll
                for (int mt = 0; mt < 4; mt++)
#pragma unroll
                    for (int nt = 0; nt < 2; nt++)
                        wmma::mma_sync(acc[mt][nt], af[mt], bf[nt], acc[mt][nt]);
            }
        }
        __syncthreads();
    }

    // ---- fused epilogue via per-warp smem staging
    const int er  = lane >> 1;
    const int ec0 = (lane & 1) * 8;
#pragma unroll
    for (int mt = 0; mt < 4; mt++) {
#pragma unroll
        for (int nt = 0; nt < 2; nt++) {
#pragma unroll
            for (int e = 0; e < acc[mt][nt].num_elements; e++)
                acc[mt][nt].x[e] *= alpha;
            wmma::store_matrix_sync(&stg[wid][0][0], acc[mt][nt], 20, wmma::mem_row_major);
            __syncwarp();
            long grow = cRow + warp_m * 64 + mt * 16 + er;
            long gcol = cCol + warp_n * 32 + nt * 16 + ec0;
#pragma unroll
            for (int j = 0; j < 8; j++) {
                float v = stg[wid][er][ec0 + j];
                if (HAS_BIAS) v += bias[gcol + j];
                if (DO_GELU)  v = 0.5f * v * (1.0f + erff(v * 0.70710678118f));
                if (HAS_RES)  v = Res[grow * N + gcol + j] + res_scale * v;
                if (ROUND_OUT) v = rtf(v);
                C[grow * N + gcol + j] = v;
                if (DUAL_OUT) C2[grow * N + gcol + j] = rtf(v);
            }
            __syncwarp();
        }
    }
}

// ---------------------------------------------------------------------------
// Causal row softmax, in place; output rounded to tf32 (it feeds a GEMM).
// ---------------------------------------------------------------------------
__global__ void softmax_causal(float* __restrict__ s) {
    const int row = blockIdx.x;
    const int q   = row % TT;
    float* p = s + (long)row * TT;
    const int n = q + 1;
    const int tid = threadIdx.x;
    __shared__ float red[256];

    float m = -INFINITY;
    for (int j = tid; j < n; j += 256) m = fmaxf(m, p[j]);
    red[tid] = m; __syncthreads();
    for (int st = 128; st > 0; st >>= 1) {
        if (tid < st) red[tid] = fmaxf(red[tid], red[tid + st]);
        __syncthreads();
    }
    m = red[0]; __syncthreads();

    float sum = 0.f;
    for (int j = tid; j < n; j += 256) {
        float e = __expf(p[j] - m);
        p[j] = e;
        sum += e;
    }
    red[tid] = sum; __syncthreads();
    for (int st = 128; st > 0; st >>= 1) {
        if (tid < st) red[tid] += red[tid + st];
        __syncthreads();
    }
    const float inv = 1.0f / red[0];
    __syncthreads();

    for (int j = tid; j < n; j += 256) p[j] = rtf(p[j] * inv);
    for (int j = n + tid; j < TT; j += 256) p[j] = 0.f;
}

// ---------------------------------------------------------------------------
// Launch
// ---------------------------------------------------------------------------
extern "C" void kernel_launch(void* const* d_in, const int* in_sizes, int n_in,
                              void* d_out, int out_size) {
    const int*   idx  = (const int*)d_in[0];
    const float* tok  = (const float*)d_in[1];
    const float* pos  = (const float*)d_in[2];
    const float* Wq   = (const float*)d_in[3];
    const float* Wk   = (const float*)d_in[4];
    const float* Wv   = (const float*)d_in[5];
    const float* W1   = (const float*)d_in[6];
    const float* b1   = (const float*)d_in[7];
    const float* W2   = (const float*)d_in[8];
    const float* b2   = (const float*)d_in[9];
    const float* Wout = (const float*)d_in[10];
    const float* bout = (const float*)d_in[11];
    float* out = (float*)d_out;

    float *x, *xt, *q, *k, *v, *s, *h;
    float *wq, *wk, *wv, *w1, *w2, *wo;
    cudaGetSymbolAddress((void**)&x,  g_x);
    cudaGetSymbolAddress((void**)&xt, g_xt);
    cudaGetSymbolAddress((void**)&q,  g_q);
    cudaGetSymbolAddress((void**)&k,  g_k);
    cudaGetSymbolAddress((void**)&v,  g_v);
    cudaGetSymbolAddress((void**)&s,  g_s);
    cudaGetSymbolAddress((void**)&h,  g_h);
    cudaGetSymbolAddress((void**)&wq, g_wq);
    cudaGetSymbolAddress((void**)&wk, g_wk);
    cudaGetSymbolAddress((void**)&wv, g_wv);
    cudaGetSymbolAddress((void**)&w1, g_w1);
    cudaGetSymbolAddress((void**)&w2, g_w2);
    cudaGetSymbolAddress((void**)&wo, g_wo);

    // 0. round weights to tf32 scratch
    {
        auto rp = [](const float* in, float* outp, long n) {
            int n4 = (int)(n / 4);
            round_tf32_kernel<<<(n4 + 255) / 256, 256>>>(in, outp, n4);
        };
        rp(Wq,   wq, (long)D_MODEL * D_MODEL);
        rp(Wk,   wk, (long)D_MODEL * D_MODEL);
        rp(Wv,   wv, (long)D_MODEL * D_MODEL);
        rp(W1,   w1, (long)D_MODEL * D_FF);
        rp(W2,   w2, (long)D_FF * D_MODEL);
        rp(Wout, wo, (long)D_MODEL * VOCAB);
    }

    // 1. embeddings -> g_x (fp32) + g_xt (tf32)
    {
        int n4 = (M_TOT * D_MODEL) / 4;
        embed_kernel<<<(n4 + 255) / 256, 256>>>(idx, tok, pos);
    }

    // 2. q,k,v = xt @ W{q,k,v}  (outputs tf32-rounded)
    {
        dim3 grid(D_MODEL / 128, M_TOT / 128, 1);
        tgemm<false,false,false,false,false,false,true,false><<<grid, 256>>>(xt, wq, nullptr, nullptr, q, nullptr,
            M_TOT, D_MODEL, D_MODEL, 1.0f, 0.f, 0, 0, 0, 0);
        tgemm<false,false,false,false,false,false,true,false><<<grid, 256>>>(xt, wk, nullptr, nullptr, k, nullptr,
            M_TOT, D_MODEL, D_MODEL, 1.0f, 0.f, 0, 0, 0, 0);
        tgemm<false,false,false,false,false,false,true,false><<<grid, 256>>>(xt, wv, nullptr, nullptr, v, nullptr,
            M_TOT, D_MODEL, D_MODEL, 1.0f, 0.f, 0, 0, 0, 0);
    }

    // 3. scores = (q @ k^T) / 32, lower-triangle tiles only
    {
        dim3 grid(TT / 128, TT / 128, BB);
        tgemm<true,false,false,false,true,false,false,false><<<grid, 256>>>(q, k, nullptr, nullptr, s, nullptr,
            TT, TT, D_MODEL, 1.0f / 32.0f, 0.f,
            (long)TT * D_MODEL, (long)TT * D_MODEL, (long)TT * TT, 0);
    }

    // 4. causal softmax (rounds attn to tf32)
    softmax_causal<<<BB * TT, 256>>>(s);

    // 5. x = x + 0.125*(attn @ v), K capped; dual output x + xt
    {
        dim3 grid(D_MODEL / 128, TT / 128, BB);
        tgemm<false,false,false,true,false,true,false,true><<<grid, 256>>>(s, v, nullptr, x, x, xt,
            TT, D_MODEL, TT, 1.0f, 0.125f,
            (long)TT * TT, (long)TT * D_MODEL, (long)TT * D_MODEL, (long)TT * D_MODEL);
    }

    // 6. h = gelu(xt @ W1 + b1)  (output tf32-rounded)
    {
        dim3 grid(D_FF / 128, M_TOT / 128, 1);
        tgemm<false,true,true,false,false,false,true,false><<<grid, 256>>>(xt, w1, b1, nullptr, h, nullptr,
            M_TOT, D_FF, D_MODEL, 1.0f, 0.f, 0, 0, 0, 0);
    }

    // 7. x = x + (h @ W2 + b2); dual output x + xt
    {
        dim3 grid(D_MODEL / 128, M_TOT / 128, 1);
        tgemm<false,true,false,true,false,false,false,true><<<grid, 256>>>(h, w2, b2, x, x, xt,
            M_TOT, D_MODEL, D_FF, 1.0f, 1.0f, 0, 0, 0, 0);
    }

    // 8. out = xt @ Wout + bout
    {
        dim3 grid(VOCAB / 128, M_TOT / 128, 1);
        tgemm<false,true,false,false,false,false,false,false><<<grid, 256>>>(xt, wo, bout, nullptr, out, nullptr,
            M_TOT, VOCAB, D_MODEL, 1.0f, 0.f, 0, 0, 0, 0);
    }
}

// round 9
// speedup vs baseline: 8.0668x; 4.1124x over previous
#include <cuda_runtime.h>
#include <mma.h>
#include <cuda_fp16.h>
#include <math.h>
#include <stdint.h>

using namespace nvcuda;

#define D_MODEL 1024
#define VOCAB   32000
#define BB      2
#define TT      2048
#define M_TOT   (BB * TT)      // 4096
#define D_FF    (4 * D_MODEL)  // 4096

// ---------------------------------------------------------------------------
// Scratch
// ---------------------------------------------------------------------------
__device__ float  g_x [M_TOT * D_MODEL];   // residual stream (fp32)
__device__ __half g_xh[M_TOT * D_MODEL];   // half copy of x (GEMM A)
__device__ __half g_q [M_TOT * D_MODEL];   // q pre-scaled by 1/32
__device__ __half g_k [M_TOT * D_MODEL];
__device__ __half g_v [M_TOT * D_MODEL];
__device__ float  g_s [BB * TT * TT];      // scores (fp32)
__device__ __half g_p [BB * TT * TT];      // attn probs (half)
__device__ __half g_h [M_TOT * D_FF];      // MLP hidden (half)
// half weights (original layouts, [K,N] row-major)
__device__ __half g_wq[D_MODEL * D_MODEL];
__device__ __half g_wk[D_MODEL * D_MODEL];
__device__ __half g_wv[D_MODEL * D_MODEL];
__device__ __half g_w1[D_MODEL * D_FF];
__device__ __half g_w2[D_FF * D_MODEL];
__device__ __half g_wo[D_MODEL * VOCAB];

// ---------------------------------------------------------------------------
// helpers
// ---------------------------------------------------------------------------
__device__ __forceinline__ void cp_async16(void* dst, const void* src) {
    unsigned d = (unsigned)__cvta_generic_to_shared(dst);
    asm volatile("cp.async.ca.shared.global [%0], [%1], 16;\n" :: "r"(d), "l"(src));
}
__device__ __forceinline__ void cp_commit() { asm volatile("cp.async.commit_group;\n"); }
__device__ __forceinline__ void cp_wait1()  { asm volatile("cp.async.wait_group 1;\n"); }

// ---------------------------------------------------------------------------
// fp32 -> fp16 conversion prepass (weights)
// ---------------------------------------------------------------------------
__global__ void f2h_kernel(const float* __restrict__ in, __half* __restrict__ out, int n8) {
    int i = blockIdx.x * blockDim.x + threadIdx.x;
    if (i >= n8) return;
    const float4 a = reinterpret_cast<const float4*>(in)[i * 2 + 0];
    const float4 b = reinterpret_cast<const float4*>(in)[i * 2 + 1];
    __half2 h0 = __floats2half2_rn(a.x, a.y);
    __half2 h1 = __floats2half2_rn(a.z, a.w);
    __half2 h2 = __floats2half2_rn(b.x, b.y);
    __half2 h3 = __floats2half2_rn(b.z, b.w);
    uint4 pk;
    pk.x = *reinterpret_cast<unsigned*>(&h0);
    pk.y = *reinterpret_cast<unsigned*>(&h1);
    pk.z = *reinterpret_cast<unsigned*>(&h2);
    pk.w = *reinterpret_cast<unsigned*>(&h3);
    reinterpret_cast<uint4*>(out)[i] = pk;
}

// ---------------------------------------------------------------------------
// Embedding: x = tok[idx] + pos ; fp32 + half copies
// ---------------------------------------------------------------------------
__global__ void embed_kernel(const int* __restrict__ idx,
                             const float* __restrict__ tok,
                             const float* __restrict__ pos) {
    int i = blockIdx.x * blockDim.x + threadIdx.x;
    int n4 = (M_TOT * D_MODEL) / 4;
    if (i >= n4) return;
    int e   = i * 4;
    int row = e / D_MODEL;
    int d   = e % D_MODEL;
    int t   = row % TT;
    int tk  = idx[row];
    const float4 a = *reinterpret_cast<const float4*>(tok + (long)tk * D_MODEL + d);
    const float4 b = *reinterpret_cast<const float4*>(pos + (long)t  * D_MODEL + d);
    float4 o;
    o.x = a.x + b.x; o.y = a.y + b.y; o.z = a.z + b.z; o.w = a.w + b.w;
    *reinterpret_cast<float4*>(g_x + e) = o;
    __half2 h0 = __floats2half2_rn(o.x, o.y);
    __half2 h1 = __floats2half2_rn(o.z, o.w);
    uint2 pk;
    pk.x = *reinterpret_cast<unsigned*>(&h0);
    pk.y = *reinterpret_cast<unsigned*>(&h1);
    *reinterpret_cast<uint2*>(g_xh + e) = pk;
}

// ---------------------------------------------------------------------------
// FP16 tensor GEMM, cp.async double-buffered, fp32 accumulation.
//   C = epi(alpha * A @ B(^T) [+bias])  [res + rs*(...)]
//   Block 128x128x64, 8 warps (2m x 4n), warp 64x32, wmma 16x16x16.
//   OUT_F32: store fp32 to C.   OUT_HALF: store half to C2.
// ---------------------------------------------------------------------------
template<bool TRANSB, bool HAS_BIAS, bool DO_GELU, bool HAS_RES,
         bool CAUSAL, bool KCAP, bool OUT_F32, bool OUT_HALF>
__global__ __launch_bounds__(256, 2)
void hgemm(const __half* __restrict__ A, const __half* __restrict__ Bm,
           const float* __restrict__ bias, const float* __restrict__ Res,
           float* __restrict__ C, __half* __restrict__ C2,
           int M, int N, int K,
           float alpha, float res_scale,
           long sA, long sB, long sC, long sR)
{
    constexpr int BM = 128, BN = 128, BK = 64;
    constexpr int LDA   = 72;                  // halves; 144B, 16B-multiple
    constexpr int LDB   = TRANSB ? 72 : 136;
    constexpr int BROWS = TRANSB ? BM : BK;

    if (CAUSAL && blockIdx.x > blockIdx.y) return;

    A  += (long)blockIdx.z * sA;
    Bm += (long)blockIdx.z * sB;
    if (OUT_F32)  C  += (long)blockIdx.z * sC;
    if (OUT_HALF) C2 += (long)blockIdx.z * sC;
    if (HAS_RES)  Res += (long)blockIdx.z * sR;

    __shared__ __half As[2][BM][LDA];
    __shared__ __half Bs[2][BROWS][LDB];
    __shared__ float  stg[8][16][20];

    const int tid  = threadIdx.x;
    const int wid  = tid / 32;
    const int lane = tid % 32;
    const int warp_m = wid % 2;
    const int warp_n = wid / 2;
    const int cRow = blockIdx.y * BM;
    const int cCol = blockIdx.x * BN;

    const int Keff = KCAP ? (K < cRow + BM ? K : cRow + BM) : K;
    const int nT = Keff / BK;

    // load coords (8 halves = 16B per cp.async)
    const int a_r0 = tid >> 3;          // 0..31, 4 reps stride 32 -> 128 rows
    const int a_c  = (tid & 7) * 8;     // 0..56 halves
    const int b_r0 = tid >> 4;          // 0..15, 4 reps stride 16 -> 64 rows
    const int b_c  = (tid & 15) * 8;    // 0..120 halves

    const __half* Abase = A + (long)cRow * K + a_c;

    {
#pragma unroll
        for (int i = 0; i < 4; i++)
            cp_async16(&As[0][a_r0 + 32 * i][a_c], Abase + (long)(a_r0 + 32 * i) * K);
        if (!TRANSB) {
#pragma unroll
            for (int i = 0; i < 4; i++)
                cp_async16(&Bs[0][b_r0 + 16 * i][b_c], Bm + (long)(b_r0 + 16 * i) * N + cCol + b_c);
        } else {
#pragma unroll
            for (int i = 0; i < 4; i++)
                cp_async16(&Bs[0][a_r0 + 32 * i][a_c], Bm + (long)(cCol + a_r0 + 32 * i) * K + a_c);
        }
        cp_commit();
    }

    wmma::fragment<wmma::accumulator, 16, 16, 16, float> acc[4][2];
#pragma unroll
    for (int mt = 0; mt < 4; mt++)
#pragma unroll
        for (int nt = 0; nt < 2; nt++)
            wmma::fill_fragment(acc[mt][nt], 0.0f);

    for (int t = 0; t < nT; t++) {
        if (t + 1 < nT) {
            const int kt = (t + 1) * BK;
            const int nb = (t + 1) & 1;
#pragma unroll
            for (int i = 0; i < 4; i++)
                cp_async16(&As[nb][a_r0 + 32 * i][a_c], Abase + kt + (long)(a_r0 + 32 * i) * K);
            if (!TRANSB) {
#pragma unroll
                for (int i = 0; i < 4; i++)
                    cp_async16(&Bs[nb][b_r0 + 16 * i][b_c], Bm + (long)(kt + b_r0 + 16 * i) * N + cCol + b_c);
            } else {
#pragma unroll
                for (int i = 0; i < 4; i++)
                    cp_async16(&Bs[nb][a_r0 + 32 * i][a_c], Bm + (long)(cCol + a_r0 + 32 * i) * K + kt + a_c);
            }
        }
        cp_commit();
        cp_wait1();
        __syncthreads();

        const int cb = t & 1;
#pragma unroll
        for (int kk = 0; kk < BK; kk += 16) {
            wmma::fragment<wmma::matrix_a, 16, 16, 16, __half, wmma::row_major> af[4];
#pragma unroll
            for (int mt = 0; mt < 4; mt++)
                wmma::load_matrix_sync(af[mt], &As[cb][warp_m * 64 + mt * 16][kk], LDA);
            if (!TRANSB) {
                wmma::fragment<wmma::matrix_b, 16, 16, 16, __half, wmma::row_major> bf[2];
#pragma unroll
                for (int nt = 0; nt < 2; nt++)
                    wmma::load_matrix_sync(bf[nt], &Bs[cb][kk][warp_n * 32 + nt * 16], LDB);
#pragma unroll
                for (int mt = 0; mt < 4; mt++)
#pragma unroll
                    for (int nt = 0; nt < 2; nt++)
                        wmma::mma_sync(acc[mt][nt], af[mt], bf[nt], acc[mt][nt]);
            } else {
                wmma::fragment<wmma::matrix_b, 16, 16, 16, __half, wmma::col_major> bf[2];
#pragma unroll
                for (int nt = 0; nt < 2; nt++)
                    wmma::load_matrix_sync(bf[nt], &Bs[cb][warp_n * 32 + nt * 16][kk], LDB);
#pragma unroll
                for (int mt = 0; mt < 4; mt++)
#pragma unroll
                    for (int nt = 0; nt < 2; nt++)
                        wmma::mma_sync(acc[mt][nt], af[mt], bf[nt], acc[mt][nt]);
            }
        }
        __syncthreads();
    }

    // ---- fused epilogue via per-warp smem staging
    const int er  = lane >> 1;
    const int ec0 = (lane & 1) * 8;
#pragma unroll
    for (int mt = 0; mt < 4; mt++) {
#pragma unroll
        for (int nt = 0; nt < 2; nt++) {
            wmma::store_matrix_sync(&stg[wid][0][0], acc[mt][nt], 20, wmma::mem_row_major);
            __syncwarp();
            long grow = cRow + warp_m * 64 + mt * 16 + er;
            long gcol = cCol + warp_n * 32 + nt * 16 + ec0;
            float fv[8];
#pragma unroll
            for (int j = 0; j < 8; j++) {
                float v = alpha * stg[wid][er][ec0 + j];
                if (HAS_BIAS) v += bias[gcol + j];
                if (DO_GELU)  v = 0.5f * v * (1.0f + erff(v * 0.70710678118f));
                if (HAS_RES)  v = Res[grow * N + gcol + j] + res_scale * v;
                fv[j] = v;
            }
            if (OUT_F32) {
                float4 v0 = { fv[0], fv[1], fv[2], fv[3] };
                float4 v1 = { fv[4], fv[5], fv[6], fv[7] };
                *reinterpret_cast<float4*>(C + grow * N + gcol)     = v0;
                *reinterpret_cast<float4*>(C + grow * N + gcol + 4) = v1;
            }
            if (OUT_HALF) {
                __half2 h0 = __floats2half2_rn(fv[0], fv[1]);
                __half2 h1 = __floats2half2_rn(fv[2], fv[3]);
                __half2 h2 = __floats2half2_rn(fv[4], fv[5]);
                __half2 h3 = __floats2half2_rn(fv[6], fv[7]);
                uint4 pk;
                pk.x = *reinterpret_cast<unsigned*>(&h0);
                pk.y = *reinterpret_cast<unsigned*>(&h1);
                pk.z = *reinterpret_cast<unsigned*>(&h2);
                pk.w = *reinterpret_cast<unsigned*>(&h3);
                *reinterpret_cast<uint4*>(C2 + grow * N + gcol) = pk;
            }
            __syncwarp();
        }
    }
}

// ---------------------------------------------------------------------------
// Causal row softmax: reads fp32 scores, writes half probs (+ zero fill).
// ---------------------------------------------------------------------------
__global__ void softmax_causal(const float* __restrict__ s, __half* __restrict__ pout) {
    const int row = blockIdx.x;
    const int q   = row % TT;
    const float* p = s + (long)row * TT;
    __half* po = pout + (long)row * TT;
    const int n = q + 1;
    const int tid = threadIdx.x;
    __shared__ float red[256];

    float m = -INFINITY;
    for (int j = tid; j < n; j += 256) m = fmaxf(m, p[j]);
    red[tid] = m; __syncthreads();
    for (int st = 128; st > 0; st >>= 1) {
        if (tid < st) red[tid] = fmaxf(red[tid], red[tid + st]);
        __syncthreads();
    }
    m = red[0]; __syncthreads();

    float sum = 0.f;
    for (int j = tid; j < n; j += 256) sum += __expf(p[j] - m);
    red[tid] = sum; __syncthreads();
    for (int st = 128; st > 0; st >>= 1) {
        if (tid < st) red[tid] += red[tid + st];
        __syncthreads();
    }
    const float inv = 1.0f / red[0];
    __syncthreads();

    for (int j = tid; j < n; j += 256)
        po[j] = __float2half_rn(__expf(p[j] - m) * inv);
    for (int j = n + tid; j < TT; j += 256)
        po[j] = __float2half_rn(0.f);
}

// ---------------------------------------------------------------------------
// Launch
// ---------------------------------------------------------------------------
extern "C" void kernel_launch(void* const* d_in, const int* in_sizes, int n_in,
                              void* d_out, int out_size) {
    const int*   idx  = (const int*)d_in[0];
    const float* tok  = (const float*)d_in[1];
    const float* pos  = (const float*)d_in[2];
    const float* Wq   = (const float*)d_in[3];
    const float* Wk   = (const float*)d_in[4];
    const float* Wv   = (const float*)d_in[5];
    const float* W1   = (const float*)d_in[6];
    const float* b1   = (const float*)d_in[7];
    const float* W2   = (const float*)d_in[8];
    const float* b2   = (const float*)d_in[9];
    const float* Wout = (const float*)d_in[10];
    const float* bout = (const float*)d_in[11];
    float* out = (float*)d_out;

    float  *x, *s;
    __half *xh, *q, *k, *v, *p, *h;
    __half *wq, *wk, *wv, *w1, *w2, *wo;
    cudaGetSymbolAddress((void**)&x,  g_x);
    cudaGetSymbolAddress((void**)&xh, g_xh);
    cudaGetSymbolAddress((void**)&q,  g_q);
    cudaGetSymbolAddress((void**)&k,  g_k);
    cudaGetSymbolAddress((void**)&v,  g_v);
    cudaGetSymbolAddress((void**)&s,  g_s);
    cudaGetSymbolAddress((void**)&p,  g_p);
    cudaGetSymbolAddress((void**)&h,  g_h);
    cudaGetSymbolAddress((void**)&wq, g_wq);
    cudaGetSymbolAddress((void**)&wk, g_wk);
    cudaGetSymbolAddress((void**)&wv, g_wv);
    cudaGetSymbolAddress((void**)&w1, g_w1);
    cudaGetSymbolAddress((void**)&w2, g_w2);
    cudaGetSymbolAddress((void**)&wo, g_wo);

    // 0. convert weights to half
    {
        auto cv = [](const float* in, __half* outp, long n) {
            int n8 = (int)(n / 8);
            f2h_kernel<<<(n8 + 255) / 256, 256>>>(in, outp, n8);
        };
        cv(Wq,   wq, (long)D_MODEL * D_MODEL);
        cv(Wk,   wk, (long)D_MODEL * D_MODEL);
        cv(Wv,   wv, (long)D_MODEL * D_MODEL);
        cv(W1,   w1, (long)D_MODEL * D_FF);
        cv(W2,   w2, (long)D_FF * D_MODEL);
        cv(Wout, wo, (long)D_MODEL * VOCAB);
    }

    // 1. embeddings -> g_x (fp32) + g_xh (half)
    {
        int n4 = (M_TOT * D_MODEL) / 4;
        embed_kernel<<<(n4 + 255) / 256, 256>>>(idx, tok, pos);
    }

    // 2. q,k,v = xh @ W{q,k,v}  (q pre-scaled by 1/32)
    {
        dim3 grid(D_MODEL / 128, M_TOT / 128, 1);
        hgemm<false,false,false,false,false,false,false,true><<<grid, 256>>>(xh, wq, nullptr, nullptr, nullptr, q,
            M_TOT, D_MODEL, D_MODEL, 1.0f / 32.0f, 0.f, 0, 0, 0, 0);
        hgemm<false,false,false,false,false,false,false,true><<<grid, 256>>>(xh, wk, nullptr, nullptr, nullptr, k,
            M_TOT, D_MODEL, D_MODEL, 1.0f, 0.f, 0, 0, 0, 0);
        hgemm<false,false,false,false,false,false,false,true><<<grid, 256>>>(xh, wv, nullptr, nullptr, nullptr, v,
            M_TOT, D_MODEL, D_MODEL, 1.0f, 0.f, 0, 0, 0, 0);
    }

    // 3. scores = q @ k^T (q already scaled), lower-triangle tiles only
    {
        dim3 grid(TT / 128, TT / 128, BB);
        hgemm<true,false,false,false,true,false,true,false><<<grid, 256>>>(q, k, nullptr, nullptr, s, nullptr,
            TT, TT, D_MODEL, 1.0f, 0.f,
            (long)TT * D_MODEL, (long)TT * D_MODEL, (long)TT * TT, 0);
    }

    // 4. causal softmax -> half probs
    softmax_causal<<<BB * TT, 256>>>(s, p);

    // 5. x = x + 0.125*(p @ v), K capped; fp32 + half outputs
    {
        dim3 grid(D_MODEL / 128, TT / 128, BB);
        hgemm<false,false,false,true,false,true,true,true><<<grid, 256>>>(p, v, nullptr, x, x, xh,
            TT, D_MODEL, TT, 1.0f, 0.125f,
            (long)TT * TT, (long)TT * D_MODEL, (long)TT * D_MODEL, (long)TT * D_MODEL);
    }

    // 6. h = gelu(xh @ W1 + b1)  (half out)
    {
        dim3 grid(D_FF / 128, M_TOT / 128, 1);
        hgemm<false,true,true,false,false,false,false,true><<<grid, 256>>>(xh, w1, b1, nullptr, nullptr, h,
            M_TOT, D_FF, D_MODEL, 1.0f, 0.f, 0, 0, 0, 0);
    }

    // 7. x = x + (h @ W2 + b2); fp32 + half outputs
    {
        dim3 grid(D_MODEL / 128, M_TOT / 128, 1);
        hgemm<false,true,false,true,false,false,true,true><<<grid, 256>>>(h, w2, b2, x, x, xh,
            M_TOT, D_MODEL, D_FF, 1.0f, 1.0f, 0, 0, 0, 0);
    }

    // 8. out = xh @ Wout + bout  (fp32 out)
    {
        dim3 grid(VOCAB / 128, M_TOT / 128, 1);
        hgemm<false,true,false,false,false,false,true,false><<<grid, 256>>>(xh, wo, bout, nullptr, out, nullptr,
            M_TOT, VOCAB, D_MODEL, 1.0f, 0.f, 0, 0, 0, 0);
    }
}